// round 2
// baseline (speedup 1.0000x reference)
#include <cuda_runtime.h>
#include <cuda_bf16.h>
#include <cstdint>

#define DI __device__ __forceinline__

// Problem dims
constexpr int Bn  = 64;
constexpr int Tn  = 2048;
constexpr int Dn  = 1024;
constexpr int H1n = 512;
constexpr int H2n = 32;
constexpr int MTOT = Bn * Tn;        // 131072 rows

// GEMM1 tiling
constexpr int MT  = 64;              // rows per CTA
constexpr int KC  = 64;              // K chunk
constexpr int NKC = Dn / KC;         // 16 chunks
constexpr int WSTR = 520;            // W1 smem row stride (bf16 elems), 1040 B
constexpr int ASTR = 72;             // A smem row stride (bf16 elems), 144 B

// smem layout (bytes)
constexpr int W_STAGE    = MT * WSTR * 2;          // 66560
constexpr int SMEM_W     = 0;
constexpr int A_STAGE    = MT * ASTR * 2;          // 9216
constexpr int SMEM_A     = SMEM_W + 2 * W_STAGE;   // 133120
constexpr int SMEM_W2    = SMEM_A + 2 * A_STAGE;   // 151552  (512 x 40 bf16)
constexpr int SMEM_B1    = SMEM_W2 + H1n * 40 * 2; // 192512  (512 f32)
constexpr int SMEM_H2    = SMEM_B1 + H1n * 4;      // 194560  (64 x 33 f32)
constexpr int SMEM_TOTAL = SMEM_H2 + MT * 33 * 4;  // 203008

// device scratch (no cudaMalloc allowed)
__device__ __nv_bfloat16 g_W1b[Dn * H1n];
__device__ __nv_bfloat16 g_W2b[H1n * H2n];
__device__ float         g_logits[MTOT];

// ---------------- PTX helpers ----------------
DI uint32_t smem_u32(const void* p) { return (uint32_t)__cvta_generic_to_shared(p); }

DI void ldsm4(uint32_t* r, uint32_t addr) {
    asm volatile("ldmatrix.sync.aligned.m8n8.x4.shared.b16 {%0,%1,%2,%3}, [%4];\n"
                 : "=r"(r[0]), "=r"(r[1]), "=r"(r[2]), "=r"(r[3]) : "r"(addr));
}
DI void ldsm4t(uint32_t* r, uint32_t addr) {
    asm volatile("ldmatrix.sync.aligned.m8n8.x4.trans.shared.b16 {%0,%1,%2,%3}, [%4];\n"
                 : "=r"(r[0]), "=r"(r[1]), "=r"(r[2]), "=r"(r[3]) : "r"(addr));
}
DI void ldsm2t(uint32_t* r, uint32_t addr) {
    asm volatile("ldmatrix.sync.aligned.m8n8.x2.trans.shared.b16 {%0,%1}, [%2];\n"
                 : "=r"(r[0]), "=r"(r[1]) : "r"(addr));
}
DI void mma_bf16(float* c, const uint32_t* a, const uint32_t* b) {
    asm volatile("mma.sync.aligned.m16n8k16.row.col.f32.bf16.bf16.f32 "
                 "{%0,%1,%2,%3}, {%4,%5,%6,%7}, {%8,%9}, {%0,%1,%2,%3};\n"
                 : "+f"(c[0]), "+f"(c[1]), "+f"(c[2]), "+f"(c[3])
                 : "r"(a[0]), "r"(a[1]), "r"(a[2]), "r"(a[3]), "r"(b[0]), "r"(b[1]));
}
DI void cp16(uint32_t dst, const void* src) {
    asm volatile("cp.async.cg.shared.global [%0], [%1], 16;\n" :: "r"(dst), "l"(src));
}
DI void cp_commit() { asm volatile("cp.async.commit_group;\n"); }
DI void cp_wait1()  { asm volatile("cp.async.wait_group 1;\n"); }
DI void cp_wait0()  { asm volatile("cp.async.wait_group 0;\n"); }

DI uint32_t pack2(float x, float y) {
    __nv_bfloat162 h = __floats2bfloat162_rn(x, y);
    return *reinterpret_cast<uint32_t*>(&h);
}

// ---------------- prologue: convert W1/W2 to bf16 ----------------
__global__ void convert_kernel(const float* __restrict__ W1, const float* __restrict__ W2) {
    int i = blockIdx.x * 256 + threadIdx.x;
    if (i < Dn * H1n) g_W1b[i] = __float2bfloat16(W1[i]);
    if (i < H1n * H2n) g_W2b[i] = __float2bfloat16(W2[i]);
}

// ---------------- fused MLP kernel ----------------
__global__ __launch_bounds__(512, 1) void fused_mlp_kernel(
    const float* __restrict__ A,       // [MTOT, Dn] fp32
    const int*   __restrict__ seq_len, // [Bn]
    const float* __restrict__ b1,      // [H1n]
    const float* __restrict__ b2,      // [H2n]
    const float* __restrict__ W3,      // [H2n]
    const float* __restrict__ b3)      // [1]
{
    extern __shared__ char smem[];
    __nv_bfloat16* W2s = (__nv_bfloat16*)(smem + SMEM_W2);
    float* b1s = (float*)(smem + SMEM_B1);
    float* h2s = (float*)(smem + SMEM_H2);

    const int tid  = threadIdx.x;
    const int lane = tid & 31;
    const int wid  = tid >> 5;           // 0..15
    const int m0   = blockIdx.x * MT;

    const uint32_t wbase = smem_u32(smem + SMEM_W);
    const uint32_t abase = smem_u32(smem + SMEM_A);

    // load b1 to smem
    b1s[tid] = b1[tid];
    // load W2 (bf16) to padded smem [512][40]
    {
        const uint4* src = (const uint4*)g_W2b; // 2048 x 16B
        for (int i = tid; i < 2048; i += 512) {
            int r = i >> 2, c = i & 3;
            uint4 v = src[i];
            *(uint4*)&W2s[r * 40 + c * 8] = v;
        }
    }

    // ---- GEMM1: acc[64,512] = A_tile[64,1024] @ W1 ----
    const int wm = wid & 1;              // M: 2 x 32
    const int wn = wid >> 1;             // N: 8 x 64

    float acc[2][8][4];
    #pragma unroll
    for (int i = 0; i < 2; i++)
        #pragma unroll
        for (int j = 0; j < 8; j++)
            #pragma unroll
            for (int k = 0; k < 4; k++) acc[i][j][k] = 0.f;

    // per-thread load indices
    const int ar  = tid >> 3;                   // A row 0..63
    const int ac  = (tid & 7) * 8;              // A col within chunk
    const float* Abase = A + (size_t)(m0 + ar) * Dn + ac;
    const int wr  = tid >> 3;                   // W row 0..63
    const int wc0 = tid & 7;                    // W 16B-chunk base

    // ldsm offsets (bytes, within a stage)
    uint32_t aoff[2], boff[4];
    #pragma unroll
    for (int ms = 0; ms < 2; ms++)
        aoff[ms] = ((wm * 32 + ms * 16 + (lane & 15)) * ASTR + (lane >> 4) * 8) * 2;
    #pragma unroll
    for (int np = 0; np < 4; np++)
        boff[np] = ((lane & 15) * WSTR + wn * 64 + np * 16 + (lane >> 4) * 8) * 2;

    float regA[2][8];

    auto ldA = [&](int kc, float* r) {
        const float4* p = (const float4*)(Abase + kc * KC);
        float4 v0 = p[0], v1 = p[1];
        r[0]=v0.x; r[1]=v0.y; r[2]=v0.z; r[3]=v0.w;
        r[4]=v1.x; r[5]=v1.y; r[6]=v1.z; r[7]=v1.w;
    };
    auto stA = [&](int stage, const float* r) {
        uint4 v;
        v.x = pack2(r[0], r[1]); v.y = pack2(r[2], r[3]);
        v.z = pack2(r[4], r[5]); v.w = pack2(r[6], r[7]);
        *(uint4*)(smem + SMEM_A + stage * A_STAGE + ar * (ASTR * 2) + ac * 2) = v;
    };
    auto cpW = [&](int kc, int stage) {
        const __nv_bfloat16* src = g_W1b + (size_t)(kc * KC + wr) * H1n;
        uint32_t dst = wbase + stage * W_STAGE + wr * (WSTR * 2);
        #pragma unroll
        for (int j = 0; j < 8; j++) {
            int c16 = wc0 + 8 * j;
            cp16(dst + c16 * 16, src + c16 * 8);
        }
    };
    auto compute = [&](int stage) {
        const uint32_t as = abase + stage * A_STAGE;
        const uint32_t ws = wbase + stage * W_STAGE;
        #pragma unroll
        for (int ks = 0; ks < 4; ks++) {
            uint32_t a[2][4];
            ldsm4(a[0], as + aoff[0] + ks * 32);
            ldsm4(a[1], as + aoff[1] + ks * 32);
            #pragma unroll
            for (int np = 0; np < 4; np++) {
                uint32_t bf[4];
                ldsm4t(bf, ws + boff[np] + ks * 16 * (WSTR * 2));
                mma_bf16(acc[0][2*np],   a[0], bf);
                mma_bf16(acc[0][2*np+1], a[0], bf + 2);
                mma_bf16(acc[1][2*np],   a[1], bf);
                mma_bf16(acc[1][2*np+1], a[1], bf + 2);
            }
        }
    };

    // pipeline prologue
    ldA(0, regA[0]);
    cpW(0, 0);
    cp_commit();

    #pragma unroll 2
    for (int kc = 0; kc < NKC; kc++) {
        const int cur = kc & 1;
        stA(cur, regA[cur]);
        if (kc + 1 < NKC) {
            ldA(kc + 1, regA[(kc + 1) & 1]);
            cpW(kc + 1, (kc + 1) & 1);
            cp_commit();
            cp_wait1();
        } else {
            cp_wait0();
        }
        __syncthreads();
        compute(cur);
        __syncthreads();
    }

    // ---- epilogue 1: +b1, relu, store h (bf16) to smem (aliases W stage0) ----
    #pragma unroll
    for (int ms = 0; ms < 2; ms++) {
        #pragma unroll
        for (int ns = 0; ns < 8; ns++) {
            float* c = acc[ms][ns];
            int r0  = wm * 32 + ms * 16 + (lane >> 2);
            int col = wn * 64 + ns * 8 + (lane & 3) * 2;
            float bx = b1s[col], by = b1s[col + 1];
            uint32_t p0 = pack2(fmaxf(c[0] + bx, 0.f), fmaxf(c[1] + by, 0.f));
            uint32_t p1 = pack2(fmaxf(c[2] + bx, 0.f), fmaxf(c[3] + by, 0.f));
            *(uint32_t*)(smem + r0 * (WSTR * 2) + col * 2)       = p0;
            *(uint32_t*)(smem + (r0 + 8) * (WSTR * 2) + col * 2) = p1;
        }
    }
    __syncthreads();

    // ---- GEMM2: h2[64,32] = h[64,512] @ W2[512,32] ----
    const int wm2 = wid & 3;   // M: 4 x 16
    const int wn2 = wid >> 2;  // N: 4 x 8
    float acc2[4] = {0.f, 0.f, 0.f, 0.f};
    const uint32_t habase  = smem_u32(smem) +
        ((wm2 * 16 + (lane & 15)) * WSTR + (lane >> 4) * 8) * 2;
    const uint32_t w2base = smem_u32(W2s) + ((lane & 15) * 40 + wn2 * 8) * 2;
    #pragma unroll
    for (int ks = 0; ks < 32; ks++) {
        uint32_t a[4], b[2];
        ldsm4(a, habase + ks * 32);
        ldsm2t(b, w2base + ks * 16 * 80);
        mma_bf16(acc2, a, b);
    }
    {
        int row = wm2 * 16 + (lane >> 2);
        int col = wn2 * 8 + (lane & 3) * 2;
        float bx = b2[col], by = b2[col + 1];
        h2s[row * 33 + col]           = acc2[0] + bx;
        h2s[row * 33 + col + 1]       = acc2[1] + by;
        h2s[(row + 8) * 33 + col]     = acc2[2] + bx;
        h2s[(row + 8) * 33 + col + 1] = acc2[3] + by;
    }
    __syncthreads();

    // ---- GEMM3 + sigmoid + mask ----
    if (tid < MT) {
        float x = b3[0];
        #pragma unroll
        for (int c = 0; c < H2n; c++) x += h2s[tid * 33 + c] * W3[c];
        int gm = m0 + tid;
        int bi = gm >> 11;            // / Tn
        int tt = gm & (Tn - 1);
        float lg = (tt < seq_len[bi]) ? (1.f / (1.f + __expf(-x))) : -1e30f;
        g_logits[gm] = lg;
    }
}

// ---------------- per-batch top-k mean ----------------
__global__ __launch_bounds__(512) void topk_kernel(const int* __restrict__ seq_len,
                                                   float* __restrict__ out) {
    __shared__ float s[Tn];
    __shared__ float red[16];
    const int b = blockIdx.x, tid = threadIdx.x;
    for (int i = tid; i < Tn; i += 512) s[i] = g_logits[b * Tn + i];
    __syncthreads();

    // bitonic sort, descending
    for (int k = 2; k <= Tn; k <<= 1) {
        for (int j = k >> 1; j > 0; j >>= 1) {
            for (int t = tid; t < Tn; t += 512) {
                int ixj = t ^ j;
                if (ixj > t) {
                    float a = s[t], c = s[ixj];
                    bool dir = ((t & k) == 0);
                    if ((a < c) == dir) { s[t] = c; s[ixj] = a; }
                }
            }
            __syncthreads();
        }
    }

    int k = seq_len[b] / 16 + 1;       // 2..129
    float v = (tid < k) ? s[tid] : 0.f;
    #pragma unroll
    for (int o = 16; o > 0; o >>= 1) v += __shfl_down_sync(0xFFFFFFFFu, v, o);
    if ((tid & 31) == 0) red[tid >> 5] = v;
    __syncthreads();
    if (tid == 0) {
        float tot = 0.f;
        #pragma unroll
        for (int i = 0; i < 16; i++) tot += red[i];
        out[b] = tot / (float)k;
    }
}

// ---------------- launch ----------------
extern "C" void kernel_launch(void* const* d_in, const int* in_sizes, int n_in,
                              void* d_out, int out_size) {
    const float* avf = (const float*)d_in[0];
    const int*   seq = (const int*)d_in[1];
    const float* W1  = (const float*)d_in[2];
    const float* b1  = (const float*)d_in[3];
    const float* W2  = (const float*)d_in[4];
    const float* b2  = (const float*)d_in[5];
    const float* W3  = (const float*)d_in[6];
    const float* b3  = (const float*)d_in[7];
    float* out = (float*)d_out;

    static bool attr_set = false;
    if (!attr_set) {
        cudaFuncSetAttribute(fused_mlp_kernel,
                             cudaFuncAttributeMaxDynamicSharedMemorySize, SMEM_TOTAL);
        attr_set = true;
    }

    convert_kernel<<<(Dn * H1n + 255) / 256, 256>>>(W1, W2);
    fused_mlp_kernel<<<MTOT / MT, 512, SMEM_TOTAL>>>(avf, seq, b1, b2, W3, b3);
    topk_kernel<<<Bn, 512>>>(seq, out);
}

// round 3
// speedup vs baseline: 1.0040x; 1.0040x over previous
#include <cuda_runtime.h>
#include <cuda_bf16.h>
#include <cstdint>

#define DI __device__ __forceinline__

// Problem dims
constexpr int Bn  = 64;
constexpr int Tn  = 2048;
constexpr int Dn  = 1024;
constexpr int H1n = 512;
constexpr int H2n = 32;
constexpr int MTOT = Bn * Tn;        // 131072 rows

// GEMM1 tiling
constexpr int MT  = 64;              // rows per CTA
constexpr int KC  = 64;              // K chunk
constexpr int NKC = Dn / KC;         // 16 chunks
constexpr int WSTR = 520;            // W1 smem row stride (bf16 elems), 1040 B
constexpr int ASTR = 72;             // A smem row stride (bf16 elems), 144 B

// smem layout (bytes)
constexpr int W_STAGE    = MT * WSTR * 2;          // 66560
constexpr int SMEM_W     = 0;
constexpr int A_STAGE    = MT * ASTR * 2;          // 9216
constexpr int SMEM_A     = SMEM_W + 2 * W_STAGE;   // 133120
constexpr int SMEM_W2    = SMEM_A + 2 * A_STAGE;   // 151552  (512 x 40 bf16)
constexpr int SMEM_B1    = SMEM_W2 + H1n * 40 * 2; // 192512  (512 f32)
constexpr int SMEM_H2    = SMEM_B1 + H1n * 4;      // 194560  (64 x 33 f32)
constexpr int SMEM_TOTAL = SMEM_H2 + MT * 33 * 4;  // 203008

// device scratch (no cudaMalloc allowed)
__device__ __nv_bfloat16 g_W1b[Dn * H1n];
__device__ __nv_bfloat16 g_W2b[H1n * H2n];
__device__ float         g_logits[MTOT];

// ---------------- PTX helpers ----------------
DI uint32_t smem_u32(const void* p) { return (uint32_t)__cvta_generic_to_shared(p); }

DI void ldsm4(uint32_t* r, uint32_t addr) {
    asm volatile("ldmatrix.sync.aligned.m8n8.x4.shared.b16 {%0,%1,%2,%3}, [%4];\n"
                 : "=r"(r[0]), "=r"(r[1]), "=r"(r[2]), "=r"(r[3]) : "r"(addr));
}
DI void ldsm4t(uint32_t* r, uint32_t addr) {
    asm volatile("ldmatrix.sync.aligned.m8n8.x4.trans.shared.b16 {%0,%1,%2,%3}, [%4];\n"
                 : "=r"(r[0]), "=r"(r[1]), "=r"(r[2]), "=r"(r[3]) : "r"(addr));
}
DI void ldsm2t(uint32_t* r, uint32_t addr) {
    asm volatile("ldmatrix.sync.aligned.m8n8.x2.trans.shared.b16 {%0,%1}, [%2];\n"
                 : "=r"(r[0]), "=r"(r[1]) : "r"(addr));
}
DI void mma_bf16(float* c, const uint32_t* a, const uint32_t* b) {
    asm volatile("mma.sync.aligned.m16n8k16.row.col.f32.bf16.bf16.f32 "
                 "{%0,%1,%2,%3}, {%4,%5,%6,%7}, {%8,%9}, {%0,%1,%2,%3};\n"
                 : "+f"(c[0]), "+f"(c[1]), "+f"(c[2]), "+f"(c[3])
                 : "r"(a[0]), "r"(a[1]), "r"(a[2]), "r"(a[3]), "r"(b[0]), "r"(b[1]));
}
DI void cp16(uint32_t dst, const void* src) {
    asm volatile("cp.async.cg.shared.global [%0], [%1], 16;\n" :: "r"(dst), "l"(src));
}
DI void cp_commit() { asm volatile("cp.async.commit_group;\n"); }
DI void cp_wait1()  { asm volatile("cp.async.wait_group 1;\n"); }
DI void cp_wait0()  { asm volatile("cp.async.wait_group 0;\n"); }

DI uint32_t pack2(float x, float y) {
    __nv_bfloat162 h = __floats2bfloat162_rn(x, y);
    return *reinterpret_cast<uint32_t*>(&h);
}

// ---------------- prologue: convert W1/W2 to bf16 ----------------
__global__ void convert_kernel(const float* __restrict__ W1, const float* __restrict__ W2) {
    int i = blockIdx.x * 256 + threadIdx.x;
    if (i < Dn * H1n) g_W1b[i] = __float2bfloat16(W1[i]);
    if (i < H1n * H2n) g_W2b[i] = __float2bfloat16(W2[i]);
}

// ---------------- fused MLP kernel ----------------
__global__ __launch_bounds__(512, 1) void fused_mlp_kernel(
    const float* __restrict__ A,       // [MTOT, Dn] fp32
    const int*   __restrict__ seq_len, // [Bn]
    const float* __restrict__ b1,      // [H1n]
    const float* __restrict__ b2,      // [H2n]
    const float* __restrict__ W3,      // [H2n]
    const float* __restrict__ b3)      // [1]
{
    extern __shared__ char smem[];
    __nv_bfloat16* W2s = (__nv_bfloat16*)(smem + SMEM_W2);
    float* b1s = (float*)(smem + SMEM_B1);
    float* h2s = (float*)(smem + SMEM_H2);

    const int tid  = threadIdx.x;
    const int lane = tid & 31;
    const int wid  = tid >> 5;           // 0..15
    const int m0   = blockIdx.x * MT;

    const uint32_t wbase = smem_u32(smem + SMEM_W);
    const uint32_t abase = smem_u32(smem + SMEM_A);

    // load b1 to smem
    b1s[tid] = b1[tid];
    // load W2 (bf16) to padded smem [512][40]
    {
        const uint4* src = (const uint4*)g_W2b; // 2048 x 16B
        for (int i = tid; i < 2048; i += 512) {
            int r = i >> 2, c = i & 3;
            uint4 v = src[i];
            *(uint4*)&W2s[r * 40 + c * 8] = v;
        }
    }

    // ---- GEMM1: acc[64,512] = A_tile[64,1024] @ W1 ----
    const int wm = wid & 1;              // M: 2 x 32
    const int wn = wid >> 1;             // N: 8 x 64

    float acc[2][8][4];
    #pragma unroll
    for (int i = 0; i < 2; i++)
        #pragma unroll
        for (int j = 0; j < 8; j++)
            #pragma unroll
            for (int k = 0; k < 4; k++) acc[i][j][k] = 0.f;

    // per-thread load indices
    const int ar  = tid >> 3;                   // A row 0..63
    const int ac  = (tid & 7) * 8;              // A col within chunk
    const float* Abase = A + (size_t)(m0 + ar) * Dn + ac;
    const int wr  = tid >> 3;                   // W row 0..63
    const int wc0 = tid & 7;                    // W 16B-chunk base

    // ldsm offsets (bytes, within a stage)
    uint32_t aoff[2], boff[4];
    #pragma unroll
    for (int ms = 0; ms < 2; ms++)
        aoff[ms] = ((wm * 32 + ms * 16 + (lane & 15)) * ASTR + (lane >> 4) * 8) * 2;
    #pragma unroll
    for (int np = 0; np < 4; np++)
        boff[np] = ((lane & 15) * WSTR + wn * 64 + np * 16 + (lane >> 4) * 8) * 2;

    float regA[2][8];

    auto ldA = [&](int kc, float* r) {
        const float4* p = (const float4*)(Abase + kc * KC);
        float4 v0 = p[0], v1 = p[1];
        r[0]=v0.x; r[1]=v0.y; r[2]=v0.z; r[3]=v0.w;
        r[4]=v1.x; r[5]=v1.y; r[6]=v1.z; r[7]=v1.w;
    };
    auto stA = [&](int stage, const float* r) {
        uint4 v;
        v.x = pack2(r[0], r[1]); v.y = pack2(r[2], r[3]);
        v.z = pack2(r[4], r[5]); v.w = pack2(r[6], r[7]);
        *(uint4*)(smem + SMEM_A + stage * A_STAGE + ar * (ASTR * 2) + ac * 2) = v;
    };
    auto cpW = [&](int kc, int stage) {
        const __nv_bfloat16* src = g_W1b + (size_t)(kc * KC + wr) * H1n;
        uint32_t dst = wbase + stage * W_STAGE + wr * (WSTR * 2);
        #pragma unroll
        for (int j = 0; j < 8; j++) {
            int c16 = wc0 + 8 * j;
            cp16(dst + c16 * 16, src + c16 * 8);
        }
    };
    auto compute = [&](int stage) {
        const uint32_t as = abase + stage * A_STAGE;
        const uint32_t ws = wbase + stage * W_STAGE;
        #pragma unroll
        for (int ks = 0; ks < 4; ks++) {
            uint32_t a[2][4];
            ldsm4(a[0], as + aoff[0] + ks * 32);
            ldsm4(a[1], as + aoff[1] + ks * 32);
            #pragma unroll
            for (int np = 0; np < 4; np++) {
                uint32_t bf[4];
                ldsm4t(bf, ws + boff[np] + ks * 16 * (WSTR * 2));
                mma_bf16(acc[0][2*np],   a[0], bf);
                mma_bf16(acc[0][2*np+1], a[0], bf + 2);
                mma_bf16(acc[1][2*np],   a[1], bf);
                mma_bf16(acc[1][2*np+1], a[1], bf + 2);
            }
        }
    };

    // pipeline prologue
    ldA(0, regA[0]);
    cpW(0, 0);
    cp_commit();

    #pragma unroll 2
    for (int kc = 0; kc < NKC; kc++) {
        const int cur = kc & 1;
        stA(cur, regA[cur]);
        if (kc + 1 < NKC) {
            ldA(kc + 1, regA[(kc + 1) & 1]);
            cpW(kc + 1, (kc + 1) & 1);
            cp_commit();
            cp_wait1();
        } else {
            cp_wait0();
        }
        __syncthreads();
        compute(cur);
        __syncthreads();
    }

    // ---- epilogue 1: +b1, relu, store h (bf16) to smem (aliases W stage0) ----
    #pragma unroll
    for (int ms = 0; ms < 2; ms++) {
        #pragma unroll
        for (int ns = 0; ns < 8; ns++) {
            float* c = acc[ms][ns];
            int r0  = wm * 32 + ms * 16 + (lane >> 2);
            int col = wn * 64 + ns * 8 + (lane & 3) * 2;
            float bx = b1s[col], by = b1s[col + 1];
            uint32_t p0 = pack2(fmaxf(c[0] + bx, 0.f), fmaxf(c[1] + by, 0.f));
            uint32_t p1 = pack2(fmaxf(c[2] + bx, 0.f), fmaxf(c[3] + by, 0.f));
            *(uint32_t*)(smem + r0 * (WSTR * 2) + col * 2)       = p0;
            *(uint32_t*)(smem + (r0 + 8) * (WSTR * 2) + col * 2) = p1;
        }
    }
    __syncthreads();

    // ---- GEMM2: h2[64,32] = h[64,512] @ W2[512,32] ----
    const int wm2 = wid & 3;   // M: 4 x 16
    const int wn2 = wid >> 2;  // N: 4 x 8
    float acc2[4] = {0.f, 0.f, 0.f, 0.f};
    const uint32_t habase  = smem_u32(smem) +
        ((wm2 * 16 + (lane & 15)) * WSTR + (lane >> 4) * 8) * 2;
    const uint32_t w2base = smem_u32(W2s) + ((lane & 15) * 40 + wn2 * 8) * 2;
    #pragma unroll
    for (int ks = 0; ks < 32; ks++) {
        uint32_t a[4], b[2];
        ldsm4(a, habase + ks * 32);
        ldsm2t(b, w2base + ks * 16 * 80);
        mma_bf16(acc2, a, b);
    }
    {
        int row = wm2 * 16 + (lane >> 2);
        int col = wn2 * 8 + (lane & 3) * 2;
        float bx = b2[col], by = b2[col + 1];
        h2s[row * 33 + col]           = acc2[0] + bx;
        h2s[row * 33 + col + 1]       = acc2[1] + by;
        h2s[(row + 8) * 33 + col]     = acc2[2] + bx;
        h2s[(row + 8) * 33 + col + 1] = acc2[3] + by;
    }
    __syncthreads();

    // ---- GEMM3 + sigmoid + mask ----
    if (tid < MT) {
        float x = b3[0];
        #pragma unroll
        for (int c = 0; c < H2n; c++) x += h2s[tid * 33 + c] * W3[c];
        int gm = m0 + tid;
        int bi = gm >> 11;            // / Tn
        int tt = gm & (Tn - 1);
        float lg = (tt < seq_len[bi]) ? (1.f / (1.f + __expf(-x))) : -1e30f;
        g_logits[gm] = lg;
    }
}

// ---------------- per-batch top-k mean ----------------
__global__ __launch_bounds__(512) void topk_kernel(const int* __restrict__ seq_len,
                                                   float* __restrict__ out) {
    __shared__ float s[Tn];
    __shared__ float red[16];
    const int b = blockIdx.x, tid = threadIdx.x;
    for (int i = tid; i < Tn; i += 512) s[i] = g_logits[b * Tn + i];
    __syncthreads();

    // bitonic sort, descending
    for (int k = 2; k <= Tn; k <<= 1) {
        for (int j = k >> 1; j > 0; j >>= 1) {
            for (int t = tid; t < Tn; t += 512) {
                int ixj = t ^ j;
                if (ixj > t) {
                    float a = s[t], c = s[ixj];
                    bool dir = ((t & k) == 0);
                    if ((a < c) == dir) { s[t] = c; s[ixj] = a; }
                }
            }
            __syncthreads();
        }
    }

    int k = seq_len[b] / 16 + 1;       // 2..129
    float v = (tid < k) ? s[tid] : 0.f;
    #pragma unroll
    for (int o = 16; o > 0; o >>= 1) v += __shfl_down_sync(0xFFFFFFFFu, v, o);
    if ((tid & 31) == 0) red[tid >> 5] = v;
    __syncthreads();
    if (tid == 0) {
        float tot = 0.f;
        #pragma unroll
        for (int i = 0; i < 16; i++) tot += red[i];
        out[b] = tot / (float)k;
    }
}

// ---------------- launch ----------------
extern "C" void kernel_launch(void* const* d_in, const int* in_sizes, int n_in,
                              void* d_out, int out_size) {
    const float* avf = (const float*)d_in[0];
    const int*   seq = (const int*)d_in[1];
    const float* W1  = (const float*)d_in[2];
    const float* b1  = (const float*)d_in[3];
    const float* W2  = (const float*)d_in[4];
    const float* b2  = (const float*)d_in[5];
    const float* W3  = (const float*)d_in[6];
    const float* b3  = (const float*)d_in[7];
    float* out = (float*)d_out;

    static bool attr_set = false;
    if (!attr_set) {
        cudaFuncSetAttribute(fused_mlp_kernel,
                             cudaFuncAttributeMaxDynamicSharedMemorySize, SMEM_TOTAL);
        attr_set = true;
    }

    convert_kernel<<<(Dn * H1n + 255) / 256, 256>>>(W1, W2);
    fused_mlp_kernel<<<MTOT / MT, 512, SMEM_TOTAL>>>(avf, seq, b1, b2, W3, b3);
    topk_kernel<<<Bn, 512>>>(seq, out);
}

// round 4
// speedup vs baseline: 1.0041x; 1.0001x over previous
#include <cuda_runtime.h>
#include <cuda_bf16.h>
#include <cstdint>

#define DI __device__ __forceinline__

// Problem dims
constexpr int Bn  = 64;
constexpr int Tn  = 2048;
constexpr int Dn  = 1024;
constexpr int H1n = 512;
constexpr int H2n = 32;
constexpr int MTOT = Bn * Tn;        // 131072 rows

// GEMM1 tiling
constexpr int MT  = 64;              // rows per CTA
constexpr int KC  = 64;              // K chunk
constexpr int NKC = Dn / KC;         // 16 chunks
constexpr int WSTR = 520;            // W1 smem row stride (bf16 elems), 1040 B
constexpr int ASTR = 72;             // A smem row stride (bf16 elems), 144 B

// smem layout (bytes)
constexpr int W_STAGE    = MT * WSTR * 2;          // 66560
constexpr int SMEM_W     = 0;
constexpr int A_STAGE    = MT * ASTR * 2;          // 9216
constexpr int SMEM_A     = SMEM_W + 2 * W_STAGE;   // 133120
constexpr int SMEM_W2    = SMEM_A + 2 * A_STAGE;   // 151552  (512 x 40 bf16)
constexpr int SMEM_B1    = SMEM_W2 + H1n * 40 * 2; // 192512  (512 f32)
constexpr int SMEM_H2    = SMEM_B1 + H1n * 4;      // 194560  (64 x 33 f32)
constexpr int SMEM_TOTAL = SMEM_H2 + MT * 33 * 4;  // 203008

// device scratch (no cudaMalloc allowed)
__device__ __nv_bfloat16 g_W1b[Dn * H1n];
__device__ __nv_bfloat16 g_W2b[H1n * H2n];
__device__ float         g_logits[MTOT];

// ---------------- PTX helpers ----------------
DI uint32_t smem_u32(const void* p) { return (uint32_t)__cvta_generic_to_shared(p); }

DI void ldsm4(uint32_t* r, uint32_t addr) {
    asm volatile("ldmatrix.sync.aligned.m8n8.x4.shared.b16 {%0,%1,%2,%3}, [%4];\n"
                 : "=r"(r[0]), "=r"(r[1]), "=r"(r[2]), "=r"(r[3]) : "r"(addr));
}
DI void ldsm4t(uint32_t* r, uint32_t addr) {
    asm volatile("ldmatrix.sync.aligned.m8n8.x4.trans.shared.b16 {%0,%1,%2,%3}, [%4];\n"
                 : "=r"(r[0]), "=r"(r[1]), "=r"(r[2]), "=r"(r[3]) : "r"(addr));
}
DI void ldsm2t(uint32_t* r, uint32_t addr) {
    asm volatile("ldmatrix.sync.aligned.m8n8.x2.trans.shared.b16 {%0,%1}, [%2];\n"
                 : "=r"(r[0]), "=r"(r[1]) : "r"(addr));
}
DI void mma_bf16(float* c, const uint32_t* a, const uint32_t* b) {
    asm volatile("mma.sync.aligned.m16n8k16.row.col.f32.bf16.bf16.f32 "
                 "{%0,%1,%2,%3}, {%4,%5,%6,%7}, {%8,%9}, {%0,%1,%2,%3};\n"
                 : "+f"(c[0]), "+f"(c[1]), "+f"(c[2]), "+f"(c[3])
                 : "r"(a[0]), "r"(a[1]), "r"(a[2]), "r"(a[3]), "r"(b[0]), "r"(b[1]));
}
DI void cp16(uint32_t dst, const void* src) {
    asm volatile("cp.async.cg.shared.global [%0], [%1], 16;\n" :: "r"(dst), "l"(src));
}
DI void cp_commit() { asm volatile("cp.async.commit_group;\n"); }
DI void cp_wait1()  { asm volatile("cp.async.wait_group 1;\n"); }
DI void cp_wait0()  { asm volatile("cp.async.wait_group 0;\n"); }

DI uint32_t pack2(float x, float y) {
    __nv_bfloat162 h = __floats2bfloat162_rn(x, y);
    return *reinterpret_cast<uint32_t*>(&h);
}

// ---------------- prologue: convert W1/W2 to bf16 ----------------
__global__ void convert_kernel(const float* __restrict__ W1, const float* __restrict__ W2) {
    int i = blockIdx.x * 256 + threadIdx.x;
    if (i < Dn * H1n) g_W1b[i] = __float2bfloat16(W1[i]);
    if (i < H1n * H2n) g_W2b[i] = __float2bfloat16(W2[i]);
}

// ---------------- fused MLP kernel ----------------
__global__ __launch_bounds__(512, 1) void fused_mlp_kernel(
    const float* __restrict__ A,       // [MTOT, Dn] fp32
    const int*   __restrict__ seq_len, // [Bn]
    const float* __restrict__ b1,      // [H1n]
    const float* __restrict__ b2,      // [H2n]
    const float* __restrict__ W3,      // [H2n]
    const float* __restrict__ b3)      // [1]
{
    extern __shared__ char smem[];
    __nv_bfloat16* W2s = (__nv_bfloat16*)(smem + SMEM_W2);
    float* b1s = (float*)(smem + SMEM_B1);
    float* h2s = (float*)(smem + SMEM_H2);

    const int tid  = threadIdx.x;
    const int lane = tid & 31;
    const int wid  = tid >> 5;           // 0..15
    const int m0   = blockIdx.x * MT;

    const uint32_t wbase = smem_u32(smem + SMEM_W);
    const uint32_t abase = smem_u32(smem + SMEM_A);

    // load b1 to smem
    b1s[tid] = b1[tid];
    // load W2 (bf16) to padded smem [512][40]
    {
        const uint4* src = (const uint4*)g_W2b; // 2048 x 16B
        for (int i = tid; i < 2048; i += 512) {
            int r = i >> 2, c = i & 3;
            uint4 v = src[i];
            *(uint4*)&W2s[r * 40 + c * 8] = v;
        }
    }

    // ---- GEMM1: acc[64,512] = A_tile[64,1024] @ W1 ----
    const int wm = wid & 1;              // M: 2 x 32
    const int wn = wid >> 1;             // N: 8 x 64

    float acc[2][8][4];
    #pragma unroll
    for (int i = 0; i < 2; i++)
        #pragma unroll
        for (int j = 0; j < 8; j++)
            #pragma unroll
            for (int k = 0; k < 4; k++) acc[i][j][k] = 0.f;

    // per-thread load indices
    const int ar  = tid >> 3;                   // A row 0..63
    const int ac  = (tid & 7) * 8;              // A col within chunk
    const float* Abase = A + (size_t)(m0 + ar) * Dn + ac;
    const int wr  = tid >> 3;                   // W row 0..63
    const int wc0 = tid & 7;                    // W 16B-chunk base

    // ldsm offsets (bytes, within a stage)
    uint32_t aoff[2], boff[4];
    #pragma unroll
    for (int ms = 0; ms < 2; ms++)
        aoff[ms] = ((wm * 32 + ms * 16 + (lane & 15)) * ASTR + (lane >> 4) * 8) * 2;
    #pragma unroll
    for (int np = 0; np < 4; np++)
        boff[np] = ((lane & 15) * WSTR + wn * 64 + np * 16 + (lane >> 4) * 8) * 2;

    float regA[2][8];

    auto ldA = [&](int kc, float* r) {
        const float4* p = (const float4*)(Abase + kc * KC);
        float4 v0 = p[0], v1 = p[1];
        r[0]=v0.x; r[1]=v0.y; r[2]=v0.z; r[3]=v0.w;
        r[4]=v1.x; r[5]=v1.y; r[6]=v1.z; r[7]=v1.w;
    };
    auto stA = [&](int stage, const float* r) {
        uint4 v;
        v.x = pack2(r[0], r[1]); v.y = pack2(r[2], r[3]);
        v.z = pack2(r[4], r[5]); v.w = pack2(r[6], r[7]);
        *(uint4*)(smem + SMEM_A + stage * A_STAGE + ar * (ASTR * 2) + ac * 2) = v;
    };
    auto cpW = [&](int kc, int stage) {
        const __nv_bfloat16* src = g_W1b + (size_t)(kc * KC + wr) * H1n;
        uint32_t dst = wbase + stage * W_STAGE + wr * (WSTR * 2);
        #pragma unroll
        for (int j = 0; j < 8; j++) {
            int c16 = wc0 + 8 * j;
            cp16(dst + c16 * 16, src + c16 * 8);
        }
    };
    auto compute = [&](int stage) {
        const uint32_t as = abase + stage * A_STAGE;
        const uint32_t ws = wbase + stage * W_STAGE;
        #pragma unroll
        for (int ks = 0; ks < 4; ks++) {
            uint32_t a[2][4];
            ldsm4(a[0], as + aoff[0] + ks * 32);
            ldsm4(a[1], as + aoff[1] + ks * 32);
            #pragma unroll
            for (int np = 0; np < 4; np++) {
                uint32_t bf[4];
                ldsm4t(bf, ws + boff[np] + ks * 16 * (WSTR * 2));
                mma_bf16(acc[0][2*np],   a[0], bf);
                mma_bf16(acc[0][2*np+1], a[0], bf + 2);
                mma_bf16(acc[1][2*np],   a[1], bf);
                mma_bf16(acc[1][2*np+1], a[1], bf + 2);
            }
        }
    };

    // pipeline prologue
    ldA(0, regA[0]);
    cpW(0, 0);
    cp_commit();

    #pragma unroll 2
    for (int kc = 0; kc < NKC; kc++) {
        const int cur = kc & 1;
        stA(cur, regA[cur]);
        if (kc + 1 < NKC) {
            ldA(kc + 1, regA[(kc + 1) & 1]);
            cpW(kc + 1, (kc + 1) & 1);
            cp_commit();
            cp_wait1();
        } else {
            cp_wait0();
        }
        __syncthreads();
        compute(cur);
        __syncthreads();
    }

    // ---- epilogue 1: +b1, relu, store h (bf16) to smem (aliases W stage0) ----
    #pragma unroll
    for (int ms = 0; ms < 2; ms++) {
        #pragma unroll
        for (int ns = 0; ns < 8; ns++) {
            float* c = acc[ms][ns];
            int r0  = wm * 32 + ms * 16 + (lane >> 2);
            int col = wn * 64 + ns * 8 + (lane & 3) * 2;
            float bx = b1s[col], by = b1s[col + 1];
            uint32_t p0 = pack2(fmaxf(c[0] + bx, 0.f), fmaxf(c[1] + by, 0.f));
            uint32_t p1 = pack2(fmaxf(c[2] + bx, 0.f), fmaxf(c[3] + by, 0.f));
            *(uint32_t*)(smem + r0 * (WSTR * 2) + col * 2)       = p0;
            *(uint32_t*)(smem + (r0 + 8) * (WSTR * 2) + col * 2) = p1;
        }
    }
    __syncthreads();

    // ---- GEMM2: h2[64,32] = h[64,512] @ W2[512,32] ----
    const int wm2 = wid & 3;   // M: 4 x 16
    const int wn2 = wid >> 2;  // N: 4 x 8
    float acc2[4] = {0.f, 0.f, 0.f, 0.f};
    const uint32_t habase  = smem_u32(smem) +
        ((wm2 * 16 + (lane & 15)) * WSTR + (lane >> 4) * 8) * 2;
    const uint32_t w2base = smem_u32(W2s) + ((lane & 15) * 40 + wn2 * 8) * 2;
    #pragma unroll
    for (int ks = 0; ks < 32; ks++) {
        uint32_t a[4], b[2];
        ldsm4(a, habase + ks * 32);
        ldsm2t(b, w2base + ks * 16 * 80);
        mma_bf16(acc2, a, b);
    }
    {
        int row = wm2 * 16 + (lane >> 2);
        int col = wn2 * 8 + (lane & 3) * 2;
        float bx = b2[col], by = b2[col + 1];
        h2s[row * 33 + col]           = acc2[0] + bx;
        h2s[row * 33 + col + 1]       = acc2[1] + by;
        h2s[(row + 8) * 33 + col]     = acc2[2] + bx;
        h2s[(row + 8) * 33 + col + 1] = acc2[3] + by;
    }
    __syncthreads();

    // ---- GEMM3 + sigmoid + mask ----
    if (tid < MT) {
        float x = b3[0];
        #pragma unroll
        for (int c = 0; c < H2n; c++) x += h2s[tid * 33 + c] * W3[c];
        int gm = m0 + tid;
        int bi = gm >> 11;            // / Tn
        int tt = gm & (Tn - 1);
        float lg = (tt < seq_len[bi]) ? (1.f / (1.f + __expf(-x))) : -1e30f;
        g_logits[gm] = lg;
    }
}

// ---------------- per-batch top-k mean ----------------
__global__ __launch_bounds__(512) void topk_kernel(const int* __restrict__ seq_len,
                                                   float* __restrict__ out) {
    __shared__ float s[Tn];
    __shared__ float red[16];
    const int b = blockIdx.x, tid = threadIdx.x;
    for (int i = tid; i < Tn; i += 512) s[i] = g_logits[b * Tn + i];
    __syncthreads();

    // bitonic sort, descending
    for (int k = 2; k <= Tn; k <<= 1) {
        for (int j = k >> 1; j > 0; j >>= 1) {
            for (int t = tid; t < Tn; t += 512) {
                int ixj = t ^ j;
                if (ixj > t) {
                    float a = s[t], c = s[ixj];
                    bool dir = ((t & k) == 0);
                    if ((a < c) == dir) { s[t] = c; s[ixj] = a; }
                }
            }
            __syncthreads();
        }
    }

    int k = seq_len[b] / 16 + 1;       // 2..129
    float v = (tid < k) ? s[tid] : 0.f;
    #pragma unroll
    for (int o = 16; o > 0; o >>= 1) v += __shfl_down_sync(0xFFFFFFFFu, v, o);
    if ((tid & 31) == 0) red[tid >> 5] = v;
    __syncthreads();
    if (tid == 0) {
        float tot = 0.f;
        #pragma unroll
        for (int i = 0; i < 16; i++) tot += red[i];
        out[b] = tot / (float)k;
    }
}

// ---------------- launch ----------------
extern "C" void kernel_launch(void* const* d_in, const int* in_sizes, int n_in,
                              void* d_out, int out_size) {
    const float* avf = (const float*)d_in[0];
    const int*   seq = (const int*)d_in[1];
    const float* W1  = (const float*)d_in[2];
    const float* b1  = (const float*)d_in[3];
    const float* W2  = (const float*)d_in[4];
    const float* b2  = (const float*)d_in[5];
    const float* W3  = (const float*)d_in[6];
    const float* b3  = (const float*)d_in[7];
    float* out = (float*)d_out;

    static bool attr_set = false;
    if (!attr_set) {
        cudaFuncSetAttribute(fused_mlp_kernel,
                             cudaFuncAttributeMaxDynamicSharedMemorySize, SMEM_TOTAL);
        attr_set = true;
    }

    convert_kernel<<<(Dn * H1n + 255) / 256, 256>>>(W1, W2);
    fused_mlp_kernel<<<MTOT / MT, 512, SMEM_TOTAL>>>(avf, seq, b1, b2, W3, b3);
    topk_kernel<<<Bn, 512>>>(seq, out);
}